// round 2
// baseline (speedup 1.0000x reference)
#include <cuda_runtime.h>

typedef unsigned long long ull;

#define Nn 4096
#define Cc 1000
#define Aa 2048

#define BM 128
#define BN 64
#define BK 16
#define NTHREADS 256

// Scratch (device globals — no runtime allocation allowed)
__device__ float g_g[(size_t)Nn * Aa];     // cv * W[label]  [N, A]
__device__ float g_t3[Nn];                 // sum_a Wy^2 * cv
__device__ float g_aug[(size_t)Nn * Cc];   // augmented logits
__device__ float g_nll[Nn];

// ---------------- packed f32x2 helpers (Blackwell FFMA2) ----------------
__device__ __forceinline__ ull ffma2(ull a, ull b, ull c) {
    ull d;
    asm("fma.rn.f32x2 %0, %1, %2, %3;" : "=l"(d) : "l"(a), "l"(b), "l"(c));
    return d;
}
__device__ __forceinline__ ull pack2(float lo, float hi) {
    ull r;
    asm("mov.b64 %0, {%1, %2};" : "=l"(r) : "f"(lo), "f"(hi));
    return r;
}
__device__ __forceinline__ float2 unpack2(ull v) {
    float2 r;
    asm("mov.b64 {%0, %1}, %2;" : "=f"(r.x), "=f"(r.y) : "l"(v));
    return r;
}

__device__ __forceinline__ int load_label(const int* labels, int n) {
    int lab = labels[n];
    lab = lab < 0 ? 0 : (lab >= Cc ? Cc - 1 : lab);
    return lab;
}

// ---------------- Kernel 1: g = cv * W[label], t3 = sum(Wy^2 * cv) ----------------
__global__ void prep_kernel(const float* __restrict__ cv,
                            const int* __restrict__ labels,
                            const float* __restrict__ weight) {
    int n = blockIdx.x;
    int lab = load_label(labels, n);
    const float* wrow = weight + (size_t)lab * Aa;
    const float* cvrow = cv + (size_t)n * Aa;
    float* grow = g_g + (size_t)n * Aa;

    float t3 = 0.f;
    for (int a = threadIdx.x * 4; a < Aa; a += blockDim.x * 4) {
        float4 w = *(const float4*)(wrow + a);
        float4 c = *(const float4*)(cvrow + a);
        float4 g;
        g.x = c.x * w.x; g.y = c.y * w.y; g.z = c.z * w.z; g.w = c.w * w.w;
        *(float4*)(grow + a) = g;
        t3 += g.x * w.x + g.y * w.y + g.z * w.z + g.w * w.w;
    }
    __shared__ float red[256];
    red[threadIdx.x] = t3;
    __syncthreads();
    for (int s = 128; s > 0; s >>= 1) {
        if (threadIdx.x < s) red[threadIdx.x] += red[threadIdx.x + s];
        __syncthreads();
    }
    if (threadIdx.x == 0) g_t3[n] = red[0];
}

// ---------------- Kernel 2: fused triple GEMM + epilogue ----------------
// Per (n,c): accL = f . w_c ; accT1 = cv . w_c^2 ; accT2 = (cv*Wy) . w_c
// logits = accL + bias ; aug = logits + 0.5*ratio*(t1 - 2 t2 + t3)
__global__ __launch_bounds__(NTHREADS) void fused3_gemm(
    const float* __restrict__ F, const float* __restrict__ CV,
    const float* __restrict__ W, const float* __restrict__ bias,
    const float* __restrict__ ratio_p, float* __restrict__ logits_out)
{
    __shared__ float sF[BK][BM];
    __shared__ float sC[BK][BM];
    __shared__ float sG[BK][BM];
    __shared__ float sW[BK][BN];
    __shared__ float sW2[BK][BN];

    const int tid = threadIdx.x;
    const int tx = tid & 15;   // column group: 4 cols each
    const int ty = tid >> 4;   // row group: 8 rows each
    const int bm = blockIdx.y * BM;
    const int bn = blockIdx.x * BN;

    // A-tile loads: 512 float4 per matrix, 2 per thread (idx = q*256 + tid)
    const int browA0 = tid >> 2;           // rows 0..63
    const int browA1 = 64 + (tid >> 2);    // rows 64..127
    const int kqA = tid & 3;
    // B-tile: 256 float4, 1 per thread
    const int browB = tid >> 2;            // 0..63
    const int kqB = tid & 3;

    ull accL[4][4], accT1[4][4], accT2[4][4];
#pragma unroll
    for (int i = 0; i < 4; i++)
#pragma unroll
        for (int j = 0; j < 4; j++) { accL[i][j] = 0ull; accT1[i][j] = 0ull; accT2[i][j] = 0ull; }

    const float* Fb = F   + (size_t)bm * Aa;
    const float* Cb = CV  + (size_t)bm * Aa;
    const float* Gb = g_g + (size_t)bm * Aa;
    const int cB = bn + browB;
    const float* Wb = W + (size_t)(cB < Cc ? cB : 0) * Aa;
    const bool wvalid = (cB < Cc);

    float4 pF0, pF1, pC0, pC1, pG0, pG1, pW;
    {
        const int k0 = kqA * 4;
        pF0 = *(const float4*)(Fb + (size_t)browA0 * Aa + k0);
        pF1 = *(const float4*)(Fb + (size_t)browA1 * Aa + k0);
        pC0 = *(const float4*)(Cb + (size_t)browA0 * Aa + k0);
        pC1 = *(const float4*)(Cb + (size_t)browA1 * Aa + k0);
        pG0 = *(const float4*)(Gb + (size_t)browA0 * Aa + k0);
        pG1 = *(const float4*)(Gb + (size_t)browA1 * Aa + k0);
        pW = wvalid ? *(const float4*)(Wb + kqB * 4) : make_float4(0.f, 0.f, 0.f, 0.f);
    }

    const int NKT = Aa / BK;  // 128
    for (int kt = 0; kt < NKT; kt++) {
        // commit prefetched tile to shared (transposed: [k][row])
#pragma unroll
        for (int e = 0; e < 4; e++) {
            sF[kqA * 4 + e][browA0] = ((const float*)&pF0)[e];
            sF[kqA * 4 + e][browA1] = ((const float*)&pF1)[e];
            sC[kqA * 4 + e][browA0] = ((const float*)&pC0)[e];
            sC[kqA * 4 + e][browA1] = ((const float*)&pC1)[e];
            sG[kqA * 4 + e][browA0] = ((const float*)&pG0)[e];
            sG[kqA * 4 + e][browA1] = ((const float*)&pG1)[e];
        }
#pragma unroll
        for (int e = 0; e < 4; e++) {
            float w = ((const float*)&pW)[e];
            sW[kqB * 4 + e][browB] = w;
            sW2[kqB * 4 + e][browB] = w * w;
        }
        __syncthreads();

        // prefetch next k-tile into registers (overlaps with compute below)
        if (kt + 1 < NKT) {
            const int k0 = (kt + 1) * BK + kqA * 4;
            pF0 = *(const float4*)(Fb + (size_t)browA0 * Aa + k0);
            pF1 = *(const float4*)(Fb + (size_t)browA1 * Aa + k0);
            pC0 = *(const float4*)(Cb + (size_t)browA0 * Aa + k0);
            pC1 = *(const float4*)(Cb + (size_t)browA1 * Aa + k0);
            pG0 = *(const float4*)(Gb + (size_t)browA0 * Aa + k0);
            pG1 = *(const float4*)(Gb + (size_t)browA1 * Aa + k0);
            const int k0b = (kt + 1) * BK + kqB * 4;
            if (wvalid) pW = *(const float4*)(Wb + k0b);
        }

#pragma unroll
        for (int kk = 0; kk < BK; kk++) {
            float4 af0 = *(const float4*)&sF[kk][ty * 8];
            float4 af1 = *(const float4*)&sF[kk][ty * 8 + 4];
            float4 ac0 = *(const float4*)&sC[kk][ty * 8];
            float4 ac1 = *(const float4*)&sC[kk][ty * 8 + 4];
            float4 ag0 = *(const float4*)&sG[kk][ty * 8];
            float4 ag1 = *(const float4*)&sG[kk][ty * 8 + 4];
            float4 w4  = *(const float4*)&sW[kk][tx * 4];
            float4 w24 = *(const float4*)&sW2[kk][tx * 4];

            ull afp[4] = { pack2(af0.x, af0.y), pack2(af0.z, af0.w),
                           pack2(af1.x, af1.y), pack2(af1.z, af1.w) };
            ull acp[4] = { pack2(ac0.x, ac0.y), pack2(ac0.z, ac0.w),
                           pack2(ac1.x, ac1.y), pack2(ac1.z, ac1.w) };
            ull agp[4] = { pack2(ag0.x, ag0.y), pack2(ag0.z, ag0.w),
                           pack2(ag1.x, ag1.y), pack2(ag1.z, ag1.w) };
            ull wd[4]  = { pack2(w4.x, w4.x),  pack2(w4.y, w4.y),
                           pack2(w4.z, w4.z),  pack2(w4.w, w4.w) };
            ull w2d[4] = { pack2(w24.x, w24.x), pack2(w24.y, w24.y),
                           pack2(w24.z, w24.z), pack2(w24.w, w24.w) };

#pragma unroll
            for (int j = 0; j < 4; j++) {
#pragma unroll
                for (int ip = 0; ip < 4; ip++) {
                    accL[ip][j]  = ffma2(afp[ip], wd[j],  accL[ip][j]);
                    accT1[ip][j] = ffma2(acp[ip], w2d[j], accT1[ip][j]);
                    accT2[ip][j] = ffma2(agp[ip], wd[j],  accT2[ip][j]);
                }
            }
        }
        __syncthreads();
    }

    // epilogue
    const float hr = 0.5f * (*ratio_p);
#pragma unroll
    for (int ip = 0; ip < 4; ip++) {
        const int n0 = bm + ty * 8 + ip * 2;
        const float t3a = g_t3[n0];
        const float t3b = g_t3[n0 + 1];
#pragma unroll
        for (int j = 0; j < 4; j++) {
            const int c = bn + tx * 4 + j;
            if (c < Cc) {
                float2 L  = unpack2(accL[ip][j]);
                float2 T1 = unpack2(accT1[ip][j]);
                float2 T2 = unpack2(accT2[ip][j]);
                const float b = bias[c];
                const float l0 = L.x + b, l1 = L.y + b;
                const float a0 = l0 + hr * (T1.x - 2.f * T2.x + t3a);
                const float a1 = l1 + hr * (T1.y - 2.f * T2.y + t3b);
                logits_out[(size_t)n0 * Cc + c] = l0;
                logits_out[(size_t)(n0 + 1) * Cc + c] = l1;
                g_aug[(size_t)n0 * Cc + c] = a0;
                g_aug[(size_t)(n0 + 1) * Cc + c] = a1;
            }
        }
    }
}

// ---------------- Kernel 3: per-row log-softmax NLL ----------------
__global__ void softmax_nll_kernel(const int* __restrict__ labels) {
    const int n = blockIdx.x;
    const float* row = g_aug + (size_t)n * Cc;
    const int tid = threadIdx.x;
    __shared__ float red[256];

    float mx = -3.4e38f;
    for (int c = tid; c < Cc; c += 256) mx = fmaxf(mx, row[c]);
    red[tid] = mx; __syncthreads();
    for (int s = 128; s > 0; s >>= 1) {
        if (tid < s) red[tid] = fmaxf(red[tid], red[tid + s]);
        __syncthreads();
    }
    mx = red[0]; __syncthreads();

    float sum = 0.f;
    for (int c = tid; c < Cc; c += 256) sum += expf(row[c] - mx);
    red[tid] = sum; __syncthreads();
    for (int s = 128; s > 0; s >>= 1) {
        if (tid < s) red[tid] += red[tid + s];
        __syncthreads();
    }
    if (tid == 0) {
        const int lab = load_label(labels, n);
        g_nll[n] = logf(red[0]) + mx - row[lab];
    }
}

// ---------------- Kernel 4: mean reduce ----------------
__global__ void finalize_kernel(float* __restrict__ out) {
    __shared__ float red[256];
    const int tid = threadIdx.x;
    float s = 0.f;
    for (int i = tid; i < Nn; i += 256) s += g_nll[i];
    red[tid] = s; __syncthreads();
    for (int st = 128; st > 0; st >>= 1) {
        if (tid < st) red[tid] += red[tid + st];
        __syncthreads();
    }
    if (tid == 0) out[0] = red[0] / (float)Nn;
}

// ---------------- launch ----------------
extern "C" void kernel_launch(void* const* d_in, const int* in_sizes, int n_in,
                              void* d_out, int out_size) {
    const float* F      = (const float*)d_in[0];
    const int*   labels = (const int*)d_in[1];
    const float* CV     = (const float*)d_in[2];
    const float* ratio  = (const float*)d_in[3];
    const float* W      = (const float*)d_in[4];
    const float* bias   = (const float*)d_in[5];
    float* out = (float*)d_out;

    // Defensive: logits occupy the LAST Nn*Cc elements of the output buffer;
    // the loss scalar lives at out[0].
    long long logits_off = (long long)out_size - (long long)Nn * Cc;
    if (logits_off < 0) logits_off = 0;
    float* logits_out = out + logits_off;

    prep_kernel<<<Nn, 256>>>(CV, labels, W);

    dim3 grid((Cc + BN - 1) / BN, Nn / BM);  // 16 x 32
    fused3_gemm<<<grid, NTHREADS>>>(F, CV, W, bias, ratio, logits_out);

    softmax_nll_kernel<<<Nn, 256>>>(labels);
    finalize_kernel<<<1, 256>>>(out);
}

// round 5
// speedup vs baseline: 4.2489x; 4.2489x over previous
#include <cuda_runtime.h>
#include <cuda_bf16.h>
#include <cstdint>

#define Nn 4096
#define Cc 1000
#define Aa 2048
#define Cpad 1024

#define BM 128
#define BN 128
#define BK 32                      // bf16 k per stage
#define NKT (Aa / BK)              // 64
#define TILE_B (128 * 64)          // 8192 B: 128 rows x 64B (32 bf16)
#define NMATS 7                    // Fhi,Flo,C,G | Whi,Wlo,W2
#define STAGE_B (NMATS * TILE_B)   // 57344
#define NSTAGE 3
#define SMEM_DYN (NSTAGE * STAGE_B)  // 172032

// -------- device scratch --------
__device__ __nv_bfloat16 g_Fhi[(size_t)Nn * Aa];
__device__ __nv_bfloat16 g_Flo[(size_t)Nn * Aa];
__device__ __nv_bfloat16 g_Cb [(size_t)Nn * Aa];
__device__ __nv_bfloat16 g_Gb [(size_t)Nn * Aa];   // -2 * cv * Wy
__device__ __nv_bfloat16 g_Whi[(size_t)Cpad * Aa];
__device__ __nv_bfloat16 g_Wlo[(size_t)Cpad * Aa];
__device__ __nv_bfloat16 g_W2 [(size_t)Cpad * Aa];
__device__ float g_t3[Nn];
__device__ float g_aug[(size_t)Nn * Cc];
__device__ float g_nll[Nn];

// -------- helpers --------
__device__ __forceinline__ uint32_t smem_u32(const void* p) {
    return (uint32_t)__cvta_generic_to_shared(const_cast<void*>(p));
}
__device__ __forceinline__ void cp16(uint32_t s, const void* g) {
    asm volatile("cp.async.cg.shared.global [%0], [%1], 16;" :: "r"(s), "l"(g));
}
__device__ __forceinline__ void cp_commit() {
    asm volatile("cp.async.commit_group;" ::: "memory");
}
__device__ __forceinline__ void ldsm4(uint32_t* r, uint32_t addr) {
    asm volatile("ldmatrix.sync.aligned.m8n8.x4.shared.b16 {%0,%1,%2,%3}, [%4];"
                 : "=r"(r[0]), "=r"(r[1]), "=r"(r[2]), "=r"(r[3]) : "r"(addr));
}
__device__ __forceinline__ void mma16816(float* d, const uint32_t* a, uint32_t b0, uint32_t b1) {
    asm volatile(
        "mma.sync.aligned.m16n8k16.row.col.f32.bf16.bf16.f32 "
        "{%0,%1,%2,%3}, {%4,%5,%6,%7}, {%8,%9}, {%0,%1,%2,%3};"
        : "+f"(d[0]), "+f"(d[1]), "+f"(d[2]), "+f"(d[3])
        : "r"(a[0]), "r"(a[1]), "r"(a[2]), "r"(a[3]), "r"(b0), "r"(b1));
}
__device__ __forceinline__ int load_label(const int* labels, int n) {
    int lab = labels[n];
    return lab < 0 ? 0 : (lab >= Cc ? Cc - 1 : lab);
}
// smem offset inside one 128x32bf16 tile (64B rows), XOR swizzle on the 4
// 16B column chunks keyed by (row>>1)&3: conflict-free for both cp.async
// stores (4 thr/row) and ldmatrix reads (8-row column reads).
__device__ __forceinline__ uint32_t tswz(int row, int c16) {
    return (uint32_t)(row * 64 + ((c16 ^ ((row >> 1) & 3)) << 4));
}

// ---------------- prep W ----------------
__global__ void prep_w(const float* __restrict__ W) {
    const int c = blockIdx.x;
    __nv_bfloat16* wh = g_Whi + (size_t)c * Aa;
    __nv_bfloat16* wl = g_Wlo + (size_t)c * Aa;
    __nv_bfloat16* w2 = g_W2  + (size_t)c * Aa;
    if (c >= Cc) {
        __nv_bfloat16 z = __float2bfloat16(0.f);
        for (int i = threadIdx.x; i < Aa; i += blockDim.x) { wh[i] = z; wl[i] = z; w2[i] = z; }
        return;
    }
    const float* wrow = W + (size_t)c * Aa;
    for (int i = threadIdx.x; i < Aa; i += blockDim.x) {
        float w = wrow[i];
        __nv_bfloat16 hi = __float2bfloat16(w);
        wh[i] = hi;
        wl[i] = __float2bfloat16(w - __bfloat162float(hi));
        w2[i] = __float2bfloat16(w * w);
    }
}

// ---------------- prep A ----------------
__global__ void prep_a(const float* __restrict__ F, const float* __restrict__ CV,
                       const int* __restrict__ labels, const float* __restrict__ W) {
    const int n = blockIdx.x;
    const int lab = load_label(labels, n);
    const float* frow = F  + (size_t)n * Aa;
    const float* crow = CV + (size_t)n * Aa;
    const float* wrow = W  + (size_t)lab * Aa;
    __nv_bfloat16* fh = g_Fhi + (size_t)n * Aa;
    __nv_bfloat16* fl = g_Flo + (size_t)n * Aa;
    __nv_bfloat16* cb = g_Cb  + (size_t)n * Aa;
    __nv_bfloat16* gb = g_Gb  + (size_t)n * Aa;

    float t3 = 0.f;
    for (int i = threadIdx.x; i < Aa; i += blockDim.x) {
        float f = frow[i];
        __nv_bfloat16 hi = __float2bfloat16(f);
        fh[i] = hi;
        fl[i] = __float2bfloat16(f - __bfloat162float(hi));
        float cv = crow[i];
        float wy = wrow[i];
        float g = cv * wy;
        cb[i] = __float2bfloat16(cv);
        gb[i] = __float2bfloat16(-2.f * g);
        t3 += g * wy;
    }
    for (int o = 16; o; o >>= 1) t3 += __shfl_xor_sync(~0u, t3, o);
    __shared__ float ws[8];
    if ((threadIdx.x & 31) == 0) ws[threadIdx.x >> 5] = t3;
    __syncthreads();
    if (threadIdx.x == 0) {
        float s = 0.f;
        for (int i = 0; i < 8; i++) s += ws[i];
        g_t3[n] = s;
    }
}

// ---------------- fused triple GEMM (mma.sync bf16) ----------------
// accL = Fhi.Whi + Fhi.Wlo + Flo.Whi    (logits, bf16-split precision)
// accS = C.W2 + G.Whi  (= t1 - 2 t2)
__global__ __launch_bounds__(256, 1)
void gemm3(const float* __restrict__ bias, const float* __restrict__ ratio_p,
           float* __restrict__ logits_out)
{
    extern __shared__ char smem[];
    const uint32_t sbase = smem_u32(smem);

    const int tid = threadIdx.x;
    const int lane = tid & 31;
    const int wid = tid >> 5;
    const int warp_m = wid >> 2;   // 0..1 (64 rows each)
    const int warp_n = wid & 3;    // 0..3 (32 cols each)
    const int bm = blockIdx.y * BM;
    const int bn = blockIdx.x * BN;

    // global row pointers (byte), row stride 4096B (2048 bf16)
    const char* mp[NMATS];
    mp[0] = (const char*)g_Fhi + (size_t)bm * 4096;
    mp[1] = (const char*)g_Flo + (size_t)bm * 4096;
    mp[2] = (const char*)g_Cb  + (size_t)bm * 4096;
    mp[3] = (const char*)g_Gb  + (size_t)bm * 4096;
    mp[4] = (const char*)g_Whi + (size_t)bn * 4096;
    mp[5] = (const char*)g_Wlo + (size_t)bn * 4096;
    mp[6] = (const char*)g_W2  + (size_t)bn * 4096;

    const int lrow = tid >> 2;          // 0..63
    const int lc16 = tid & 3;           // 16B chunk (64B of k per row-visit)
    const uint32_t so0 = tswz(lrow,      lc16);
    const uint32_t so1 = tswz(lrow + 64, lc16);
    const size_t go0 = (size_t)lrow * 4096 + lc16 * 16;
    const size_t go1 = go0 + (size_t)64 * 4096;

#define ISSUE_STAGE(KT, S)                                                    \
    do {                                                                      \
        const size_t kb = (size_t)(KT) * 64;                                  \
        const uint32_t st = sbase + (uint32_t)(S) * STAGE_B;                  \
        _Pragma("unroll")                                                     \
        for (int m_ = 0; m_ < NMATS; m_++) {                                  \
            cp16(st + m_ * TILE_B + so0, mp[m_] + go0 + kb);                  \
            cp16(st + m_ * TILE_B + so1, mp[m_] + go1 + kb);                  \
        }                                                                     \
        cp_commit();                                                          \
    } while (0)

    float aL[4][4][4], aS[4][4][4];
#pragma unroll
    for (int i = 0; i < 4; i++)
#pragma unroll
        for (int j = 0; j < 4; j++)
#pragma unroll
            for (int e = 0; e < 4; e++) { aL[i][j][e] = 0.f; aS[i][j][e] = 0.f; }

    ISSUE_STAGE(0, 0);
    ISSUE_STAGE(1, 1);

    // per-lane ldmatrix row parts
    const int lr16 = lane & 15;       // row within 16-row tile group
    const int lkhalf = lane >> 4;     // which 8-elem k half

    for (int kt = 0; kt < NKT; kt++) {
        if (kt == NKT - 1) { asm volatile("cp.async.wait_group 0;" ::: "memory"); }
        else               { asm volatile("cp.async.wait_group 1;" ::: "memory"); }
        __syncthreads();
        if (kt + 2 < NKT) ISSUE_STAGE(kt + 2, (kt + 2) % NSTAGE);

        const uint32_t st = sbase + (uint32_t)(kt % NSTAGE) * STAGE_B;

#pragma unroll
        for (int k16 = 0; k16 < 2; k16++) {
            // B fragments: mats Whi,Wlo,W2 ; np in {0,1} covers n-tiles 2np,2np+1
            uint32_t bfr[3][2][4];
#pragma unroll
            for (int m = 0; m < 3; m++)
#pragma unroll
                for (int np = 0; np < 2; np++) {
                    const int row = warp_n * 32 + np * 16 + lr16;
                    const int c16 = k16 * 2 + lkhalf;
                    ldsm4(bfr[m][np], st + (4 + m) * TILE_B + tswz(row, c16));
                }
#pragma unroll
            for (int mt = 0; mt < 4; mt++) {
                uint32_t af[4][4];
#pragma unroll
                for (int m = 0; m < 4; m++) {
                    const int row = warp_m * 64 + mt * 16 + lr16;
                    const int c16 = k16 * 2 + lkhalf;
                    ldsm4(af[m], st + m * TILE_B + tswz(row, c16));
                }
#pragma unroll
                for (int nt = 0; nt < 4; nt++) {
                    const int np = nt >> 1, sel = nt & 1;
                    const uint32_t h0 = bfr[0][np][sel], h1 = bfr[0][np][sel + 2];  // Whi
                    const uint32_t l0 = bfr[1][np][sel], l1 = bfr[1][np][sel + 2];  // Wlo
                    const uint32_t q0 = bfr[2][np][sel], q1 = bfr[2][np][sel + 2];  // W2
                    mma16816(aL[mt][nt], af[0], h0, h1);   // Fhi.Whi
                    mma16816(aL[mt][nt], af[1], h0, h1);   // Flo.Whi
                    mma16816(aL[mt][nt], af[0], l0, l1);   // Fhi.Wlo
                    mma16816(aS[mt][nt], af[2], q0, q1);   // C.W2
                    mma16816(aS[mt][nt], af[3], h0, h1);   // G.Whi
                }
            }
        }
    }

    // ---------------- epilogue ----------------
    // NOTE: logits_out may be only 4-byte aligned (out + 1) -> scalar stores.
    const float hr = 0.5f * (*ratio_p);
    const int r0 = lane >> 2;
    const int cq = (lane & 3) * 2;
#pragma unroll
    for (int mt = 0; mt < 4; mt++) {
        const int n0 = bm + warp_m * 64 + mt * 16 + r0;
        const int n1 = n0 + 8;
        const float t3a = g_t3[n0];
        const float t3b = g_t3[n1];
        float* lr0 = logits_out + (size_t)n0 * Cc;
        float* lr1 = logits_out + (size_t)n1 * Cc;
        float* ar0 = g_aug + (size_t)n0 * Cc;
        float* ar1 = g_aug + (size_t)n1 * Cc;
#pragma unroll
        for (int nt = 0; nt < 4; nt++) {
            const int c = bn + warp_n * 32 + nt * 8 + cq;
            if (c < Cc) {
                const float2 bv = *(const float2*)(bias + c);
                const float* L = aL[mt][nt];
                const float* S = aS[mt][nt];
                const float l00 = L[0] + bv.x, l01 = L[1] + bv.y;
                const float l10 = L[2] + bv.x, l11 = L[3] + bv.y;
                float2 av0 = make_float2(l00 + hr * (S[0] + t3a), l01 + hr * (S[1] + t3a));
                float2 av1 = make_float2(l10 + hr * (S[2] + t3b), l11 + hr * (S[3] + t3b));
                lr0[c] = l00; lr0[c + 1] = l01;       // scalar: 4B-aligned base
                lr1[c] = l10; lr1[c + 1] = l11;
                *(float2*)(ar0 + c) = av0;             // g_aug is 8B-aligned
                *(float2*)(ar1 + c) = av1;
            }
        }
    }
#undef ISSUE_STAGE
}

// ---------------- softmax / NLL ----------------
__global__ void softmax_nll_kernel(const int* __restrict__ labels) {
    const int n = blockIdx.x;
    const float* row = g_aug + (size_t)n * Cc;
    const int tid = threadIdx.x;
    __shared__ float red[256];

    float mx = -3.4e38f;
    for (int c = tid; c < Cc; c += 256) mx = fmaxf(mx, row[c]);
    red[tid] = mx; __syncthreads();
    for (int s = 128; s > 0; s >>= 1) {
        if (tid < s) red[tid] = fmaxf(red[tid], red[tid + s]);
        __syncthreads();
    }
    mx = red[0]; __syncthreads();

    float sum = 0.f;
    for (int c = tid; c < Cc; c += 256) sum += expf(row[c] - mx);
    red[tid] = sum; __syncthreads();
    for (int s = 128; s > 0; s >>= 1) {
        if (tid < s) red[tid] += red[tid + s];
        __syncthreads();
    }
    if (tid == 0) {
        const int lab = load_label(labels, n);
        g_nll[n] = logf(red[0]) + mx - row[lab];
    }
}

// ---------------- mean reduce ----------------
__global__ void finalize_kernel(float* __restrict__ out) {
    const int tid = threadIdx.x;
    float s = 0.f;
    for (int i = tid; i < Nn; i += 1024) s += g_nll[i];
    for (int o = 16; o; o >>= 1) s += __shfl_xor_sync(~0u, s, o);
    __shared__ float ws[32];
    if ((tid & 31) == 0) ws[tid >> 5] = s;
    __syncthreads();
    if (tid < 32) {
        float v = ws[tid];
        for (int o = 16; o; o >>= 1) v += __shfl_xor_sync(~0u, v, o);
        if (tid == 0) out[0] = v / (float)Nn;
    }
}

// ---------------- launch ----------------
extern "C" void kernel_launch(void* const* d_in, const int* in_sizes, int n_in,
                              void* d_out, int out_size) {
    const float* F      = (const float*)d_in[0];
    const int*   labels = (const int*)d_in[1];
    const float* CV     = (const float*)d_in[2];
    const float* ratio  = (const float*)d_in[3];
    const float* W      = (const float*)d_in[4];
    const float* bias   = (const float*)d_in[5];
    float* out = (float*)d_out;

    long long logits_off = (long long)out_size - (long long)Nn * Cc;
    if (logits_off < 0) logits_off = 0;
    float* logits_out = out + logits_off;

    static bool attr_set = false;
    if (!attr_set) {
        cudaFuncSetAttribute(gemm3, cudaFuncAttributeMaxDynamicSharedMemorySize, SMEM_DYN);
        attr_set = true;
    }

    prep_w<<<Cpad, 256>>>(W);
    prep_a<<<Nn, 256>>>(F, CV, labels, W);

    dim3 grid(Cpad / BN, Nn / BM);  // 8 x 32 = 256 CTAs
    gemm3<<<grid, 256, SMEM_DYN>>>(bias, ratio, logits_out);

    softmax_nll_kernel<<<Nn, 256>>>(labels);
    finalize_kernel<<<1, 1024>>>(out);
}

// round 6
// speedup vs baseline: 4.3838x; 1.0317x over previous
#include <cuda_runtime.h>
#include <cuda_bf16.h>
#include <cstdint>

#define Nn 4096
#define Cc 1000
#define Aa 2048
#define Cpad 1024

#define BM 128
#define BN 128
#define BK 32                      // bf16 k per stage
#define NKT (Aa / BK)              // 64
#define TILE_B (128 * 64)          // 8192 B: 128 rows x 64B (32 bf16)
#define NMATS 4                    // per kernel: 2 A-side + 2 B-side
#define STAGE_B (NMATS * TILE_B)   // 32768
#define NSTAGE 3
#define SMEM_DYN (NSTAGE * STAGE_B)  // 98304 (96KB per CTA, 2 CTAs/SM)

// -------- device scratch --------
__device__ __nv_bfloat16 g_Fhi[(size_t)Nn * Aa];
__device__ __nv_bfloat16 g_Flo[(size_t)Nn * Aa];
__device__ __nv_bfloat16 g_Cb [(size_t)Nn * Aa];
__device__ __nv_bfloat16 g_Gb [(size_t)Nn * Aa];   // -2 * cv * Wy
__device__ __nv_bfloat16 g_Whi[(size_t)Cpad * Aa];
__device__ __nv_bfloat16 g_Wlo[(size_t)Cpad * Aa];
__device__ __nv_bfloat16 g_W2 [(size_t)Cpad * Aa];
__device__ float g_t3[Nn];
__device__ float g_aug[(size_t)Nn * Cc];
__device__ float g_nll[Nn];

// -------- helpers --------
__device__ __forceinline__ uint32_t smem_u32(const void* p) {
    return (uint32_t)__cvta_generic_to_shared(const_cast<void*>(p));
}
__device__ __forceinline__ void cp16(uint32_t s, const void* g) {
    asm volatile("cp.async.cg.shared.global [%0], [%1], 16;" :: "r"(s), "l"(g));
}
__device__ __forceinline__ void cp_commit() {
    asm volatile("cp.async.commit_group;" ::: "memory");
}
__device__ __forceinline__ void ldsm4(uint32_t* r, uint32_t addr) {
    asm volatile("ldmatrix.sync.aligned.m8n8.x4.shared.b16 {%0,%1,%2,%3}, [%4];"
                 : "=r"(r[0]), "=r"(r[1]), "=r"(r[2]), "=r"(r[3]) : "r"(addr));
}
__device__ __forceinline__ void mma16816(float* d, const uint32_t* a, uint32_t b0, uint32_t b1) {
    asm volatile(
        "mma.sync.aligned.m16n8k16.row.col.f32.bf16.bf16.f32 "
        "{%0,%1,%2,%3}, {%4,%5,%6,%7}, {%8,%9}, {%0,%1,%2,%3};"
        : "+f"(d[0]), "+f"(d[1]), "+f"(d[2]), "+f"(d[3])
        : "r"(a[0]), "r"(a[1]), "r"(a[2]), "r"(a[3]), "r"(b0), "r"(b1));
}
__device__ __forceinline__ int load_label(const int* labels, int n) {
    int lab = labels[n];
    return lab < 0 ? 0 : (lab >= Cc ? Cc - 1 : lab);
}
// swizzled offset in one 128x32bf16 tile (64B rows)
__device__ __forceinline__ uint32_t tswz(int row, int c16) {
    return (uint32_t)(row * 64 + ((c16 ^ ((row >> 1) & 3)) << 4));
}

// ---------------- combined prep ----------------
__global__ void prep_all(const float* __restrict__ F, const float* __restrict__ CV,
                         const int* __restrict__ labels, const float* __restrict__ W) {
    const int b = blockIdx.x;
    if (b < Cpad) {
        const int c = b;
        __nv_bfloat16* wh = g_Whi + (size_t)c * Aa;
        __nv_bfloat16* wl = g_Wlo + (size_t)c * Aa;
        __nv_bfloat16* w2 = g_W2  + (size_t)c * Aa;
        if (c >= Cc) {
            __nv_bfloat16 z = __float2bfloat16(0.f);
            for (int i = threadIdx.x; i < Aa; i += blockDim.x) { wh[i] = z; wl[i] = z; w2[i] = z; }
            return;
        }
        const float* wrow = W + (size_t)c * Aa;
        for (int i = threadIdx.x; i < Aa; i += blockDim.x) {
            float w = wrow[i];
            __nv_bfloat16 hi = __float2bfloat16(w);
            wh[i] = hi;
            wl[i] = __float2bfloat16(w - __bfloat162float(hi));
            w2[i] = __float2bfloat16(w * w);
        }
    } else {
        const int n = b - Cpad;
        const int lab = load_label(labels, n);
        const float* frow = F  + (size_t)n * Aa;
        const float* crow = CV + (size_t)n * Aa;
        const float* wrow = W  + (size_t)lab * Aa;
        __nv_bfloat16* fh = g_Fhi + (size_t)n * Aa;
        __nv_bfloat16* fl = g_Flo + (size_t)n * Aa;
        __nv_bfloat16* cb = g_Cb  + (size_t)n * Aa;
        __nv_bfloat16* gb = g_Gb  + (size_t)n * Aa;

        float t3 = 0.f;
        for (int i = threadIdx.x; i < Aa; i += blockDim.x) {
            float f = frow[i];
            __nv_bfloat16 hi = __float2bfloat16(f);
            fh[i] = hi;
            fl[i] = __float2bfloat16(f - __bfloat162float(hi));
            float cv = crow[i];
            float wy = wrow[i];
            float g = cv * wy;
            cb[i] = __float2bfloat16(cv);
            gb[i] = __float2bfloat16(-2.f * g);
            t3 += g * wy;
        }
        for (int o = 16; o; o >>= 1) t3 += __shfl_xor_sync(~0u, t3, o);
        __shared__ float ws[8];
        if ((threadIdx.x & 31) == 0) ws[threadIdx.x >> 5] = t3;
        __syncthreads();
        if (threadIdx.x == 0) {
            float s = 0.f;
            for (int i = 0; i < 8; i++) s += ws[i];
            g_t3[n] = s;
        }
    }
}

// ======== shared GEMM skeleton (macro-generated mainloop) ========
// 4 matrices per kernel: A0,A1 (row tiles of 128), B0,B1 (col tiles of 128).
// One accumulator stream per kernel; per-(k16,tile): kernel-specific MMA mix.

#define GEMM_PROLOGUE(A0, A1, B0, B1)                                         \
    extern __shared__ char smem[];                                            \
    const uint32_t sbase = smem_u32(smem);                                    \
    const int tid = threadIdx.x;                                              \
    const int lane = tid & 31;                                                \
    const int wid = tid >> 5;                                                 \
    const int warp_m = wid >> 2;                                              \
    const int warp_n = wid & 3;                                               \
    const int bm = blockIdx.y * BM;                                           \
    const int bn = blockIdx.x * BN;                                           \
    const char* mp[NMATS];                                                    \
    mp[0] = (const char*)(A0) + (size_t)bm * 4096;                            \
    mp[1] = (const char*)(A1) + (size_t)bm * 4096;                            \
    mp[2] = (const char*)(B0) + (size_t)bn * 4096;                            \
    mp[3] = (const char*)(B1) + (size_t)bn * 4096;                            \
    const int lrow = tid >> 2;                                                \
    const int lc16 = tid & 3;                                                 \
    const uint32_t so0 = tswz(lrow, lc16);                                    \
    const uint32_t so1 = tswz(lrow + 64, lc16);                               \
    const size_t go0 = (size_t)lrow * 4096 + lc16 * 16;                       \
    const size_t go1 = go0 + (size_t)64 * 4096;                               \
    const int lr16 = lane & 15;                                               \
    const int lkhalf = lane >> 4;

#define ISSUE_STAGE(KT, S)                                                    \
    do {                                                                      \
        const size_t kb = (size_t)(KT) * 64;                                  \
        const uint32_t st_ = sbase + (uint32_t)(S) * STAGE_B;                 \
        _Pragma("unroll")                                                     \
        for (int m_ = 0; m_ < NMATS; m_++) {                                  \
            cp16(st_ + m_ * TILE_B + so0, mp[m_] + go0 + kb);                 \
            cp16(st_ + m_ * TILE_B + so1, mp[m_] + go1 + kb);                 \
        }                                                                     \
        cp_commit();                                                          \
    } while (0)

// MMA_BODY(af0, af1, b0fr, b1fr, nt, np, sel) — kernel specific

#define GEMM_MAINLOOP(MMA_BODY)                                               \
    ISSUE_STAGE(0, 0);                                                        \
    ISSUE_STAGE(1, 1);                                                        \
    for (int kt = 0; kt < NKT; kt++) {                                        \
        if (kt == NKT - 1) { asm volatile("cp.async.wait_group 0;" ::: "memory"); } \
        else               { asm volatile("cp.async.wait_group 1;" ::: "memory"); } \
        __syncthreads();                                                      \
        if (kt + 2 < NKT) ISSUE_STAGE(kt + 2, (kt + 2) % NSTAGE);             \
        const uint32_t st = sbase + (uint32_t)(kt % NSTAGE) * STAGE_B;        \
        _Pragma("unroll")                                                     \
        for (int k16 = 0; k16 < 2; k16++) {                                   \
            uint32_t b0fr[2][4], b1fr[2][4];                                  \
            _Pragma("unroll")                                                 \
            for (int np = 0; np < 2; np++) {                                  \
                const int row = warp_n * 32 + np * 16 + lr16;                 \
                const int c16 = k16 * 2 + lkhalf;                             \
                ldsm4(b0fr[np], st + 2 * TILE_B + tswz(row, c16));            \
                ldsm4(b1fr[np], st + 3 * TILE_B + tswz(row, c16));            \
            }                                                                 \
            _Pragma("unroll")                                                 \
            for (int mt = 0; mt < 4; mt++) {                                  \
                uint32_t af0[4], af1[4];                                      \
                {                                                             \
                    const int row = warp_m * 64 + mt * 16 + lr16;             \
                    const int c16 = k16 * 2 + lkhalf;                         \
                    ldsm4(af0, st + 0 * TILE_B + tswz(row, c16));             \
                    ldsm4(af1, st + 1 * TILE_B + tswz(row, c16));             \
                }                                                             \
                _Pragma("unroll")                                             \
                for (int nt = 0; nt < 4; nt++) {                              \
                    const int np = nt >> 1, sel = nt & 1;                     \
                    MMA_BODY(af0, af1, b0fr, b1fr, nt, np, sel);              \
                }                                                             \
            }                                                                 \
        }                                                                     \
    }

// ---------------- S kernel: acc = C.W2 + G.Whi  (= t1 - 2 t2) ----------------
// epilogue: g_aug = hr * (S + t3[n])
#define SMMA(af0, af1, b0fr, b1fr, nt, np, sel)                               \
    do {                                                                      \
        mma16816(acc[mt][nt], af0, b0fr[np][sel], b0fr[np][sel + 2]);         \
        mma16816(acc[mt][nt], af1, b1fr[np][sel], b1fr[np][sel + 2]);         \
    } while (0)

__global__ __launch_bounds__(256, 2)
void gemmS(const float* __restrict__ ratio_p)
{
    GEMM_PROLOGUE(g_Cb, g_Gb, g_W2, g_Whi)
    float acc[4][4][4];
#pragma unroll
    for (int i = 0; i < 4; i++)
#pragma unroll
        for (int j = 0; j < 4; j++)
#pragma unroll
            for (int e = 0; e < 4; e++) acc[i][j][e] = 0.f;

    GEMM_MAINLOOP(SMMA)

    const float hr = 0.5f * (*ratio_p);
    const int r0 = lane >> 2;
    const int cq = (lane & 3) * 2;
#pragma unroll
    for (int mt = 0; mt < 4; mt++) {
        const int n0 = bm + warp_m * 64 + mt * 16 + r0;
        const int n1 = n0 + 8;
        const float t3a = g_t3[n0];
        const float t3b = g_t3[n1];
        float* ar0 = g_aug + (size_t)n0 * Cc;
        float* ar1 = g_aug + (size_t)n1 * Cc;
#pragma unroll
        for (int nt = 0; nt < 4; nt++) {
            const int c = bn + warp_n * 32 + nt * 8 + cq;
            if (c < Cc) {
                const float* S = acc[mt][nt];
                float2 v0 = make_float2(hr * (S[0] + t3a), hr * (S[1] + t3a));
                float2 v1 = make_float2(hr * (S[2] + t3b), hr * (S[3] + t3b));
                *(float2*)(ar0 + c) = v0;
                *(float2*)(ar1 + c) = v1;
            }
        }
    }
}

// ---------------- L kernel: acc = Fhi.Whi + Fhi.Wlo + Flo.Whi ----------------
// epilogue: l = L + bias; aug = l + g_aug(prev, = hr*(S+t3)); write logits + aug
#define LMMA(af0, af1, b0fr, b1fr, nt, np, sel)                               \
    do {                                                                      \
        const uint32_t h0 = b0fr[np][sel], h1 = b0fr[np][sel + 2];            \
        mma16816(acc[mt][nt], af0, h0, h1);                                   \
        mma16816(acc[mt][nt], af1, h0, h1);                                   \
        mma16816(acc[mt][nt], af0, b1fr[np][sel], b1fr[np][sel + 2]);         \
    } while (0)

__global__ __launch_bounds__(256, 2)
void gemmL(const float* __restrict__ bias, float* __restrict__ logits_out)
{
    GEMM_PROLOGUE(g_Fhi, g_Flo, g_Whi, g_Wlo)
    float acc[4][4][4];
#pragma unroll
    for (int i = 0; i < 4; i++)
#pragma unroll
        for (int j = 0; j < 4; j++)
#pragma unroll
            for (int e = 0; e < 4; e++) acc[i][j][e] = 0.f;

    GEMM_MAINLOOP(LMMA)

    const int r0 = lane >> 2;
    const int cq = (lane & 3) * 2;
#pragma unroll
    for (int mt = 0; mt < 4; mt++) {
        const int n0 = bm + warp_m * 64 + mt * 16 + r0;
        const int n1 = n0 + 8;
        float* lr0 = logits_out + (size_t)n0 * Cc;
        float* lr1 = logits_out + (size_t)n1 * Cc;
        float* ar0 = g_aug + (size_t)n0 * Cc;
        float* ar1 = g_aug + (size_t)n1 * Cc;
#pragma unroll
        for (int nt = 0; nt < 4; nt++) {
            const int c = bn + warp_n * 32 + nt * 8 + cq;
            if (c < Cc) {
                const float2 bv = *(const float2*)(bias + c);
                const float2 s0 = *(const float2*)(ar0 + c);
                const float2 s1 = *(const float2*)(ar1 + c);
                const float* L = acc[mt][nt];
                const float l00 = L[0] + bv.x, l01 = L[1] + bv.y;
                const float l10 = L[2] + bv.x, l11 = L[3] + bv.y;
                lr0[c] = l00; lr0[c + 1] = l01;   // logits_out only 4B-aligned
                lr1[c] = l10; lr1[c + 1] = l11;
                *(float2*)(ar0 + c) = make_float2(l00 + s0.x, l01 + s0.y);
                *(float2*)(ar1 + c) = make_float2(l10 + s1.x, l11 + s1.y);
            }
        }
    }
}

// ---------------- softmax / NLL ----------------
__global__ void softmax_nll_kernel(const int* __restrict__ labels) {
    const int n = blockIdx.x;
    const float* row = g_aug + (size_t)n * Cc;
    const int tid = threadIdx.x;
    __shared__ float red[256];

    float mx = -3.4e38f;
    for (int c = tid; c < Cc; c += 256) mx = fmaxf(mx, row[c]);
    red[tid] = mx; __syncthreads();
    for (int s = 128; s > 0; s >>= 1) {
        if (tid < s) red[tid] = fmaxf(red[tid], red[tid + s]);
        __syncthreads();
    }
    mx = red[0]; __syncthreads();

    float sum = 0.f;
    for (int c = tid; c < Cc; c += 256) sum += expf(row[c] - mx);
    red[tid] = sum; __syncthreads();
    for (int s = 128; s > 0; s >>= 1) {
        if (tid < s) red[tid] += red[tid + s];
        __syncthreads();
    }
    if (tid == 0) {
        const int lab = load_label(labels, n);
        g_nll[n] = logf(red[0]) + mx - row[lab];
    }
}

// ---------------- mean reduce ----------------
__global__ void finalize_kernel(float* __restrict__ out) {
    const int tid = threadIdx.x;
    float s = 0.f;
    for (int i = tid; i < Nn; i += 1024) s += g_nll[i];
    for (int o = 16; o; o >>= 1) s += __shfl_xor_sync(~0u, s, o);
    __shared__ float ws[32];
    if ((tid & 31) == 0) ws[tid >> 5] = s;
    __syncthreads();
    if (tid < 32) {
        float v = ws[tid];
        for (int o = 16; o; o >>= 1) v += __shfl_xor_sync(~0u, v, o);
        if (tid == 0) out[0] = v / (float)Nn;
    }
}

// ---------------- launch ----------------
extern "C" void kernel_launch(void* const* d_in, const int* in_sizes, int n_in,
                              void* d_out, int out_size) {
    const float* F      = (const float*)d_in[0];
    const int*   labels = (const int*)d_in[1];
    const float* CV     = (const float*)d_in[2];
    const float* ratio  = (const float*)d_in[3];
    const float* W      = (const float*)d_in[4];
    const float* bias   = (const float*)d_in[5];
    float* out = (float*)d_out;

    long long logits_off = (long long)out_size - (long long)Nn * Cc;
    if (logits_off < 0) logits_off = 0;
    float* logits_out = out + logits_off;

    static bool attr_set = false;
    if (!attr_set) {
        cudaFuncSetAttribute(gemmS, cudaFuncAttributeMaxDynamicSharedMemorySize, SMEM_DYN);
        cudaFuncSetAttribute(gemmL, cudaFuncAttributeMaxDynamicSharedMemorySize, SMEM_DYN);
        attr_set = true;
    }

    prep_all<<<Cpad + Nn, 256>>>(F, CV, labels, W);

    dim3 grid(Cpad / BN, Nn / BM);  // 8 x 32 = 256 CTAs
    gemmS<<<grid, 256, SMEM_DYN>>>(ratio);
    gemmL<<<grid, 256, SMEM_DYN>>>(bias, logits_out);

    softmax_nll_kernel<<<Nn, 256>>>(labels);
    finalize_kernel<<<1, 1024>>>(out);
}